// round 11
// baseline (speedup 1.0000x reference)
#include <cuda_runtime.h>
#include <stdint.h>

#define BN_EPS 1e-5f

namespace {
constexpr int Nn = 64, C = 256, H = 56, W = 56;
constexpr int HP = H + 2, WPAD = W + 2;          // zero-padded bitplane dims
constexpr int WORDS = C / 32;                     // 8 words of channel bits
constexpr int KW = 9 * WORDS;                     // 72 (tap, word) pairs
constexpr int RS = 40;                            // smem row stride (words); 40%32=8 -> perfect banks
constexpr int TROWS = 6;                          // tile rows (4 outputs + 2 halo)
constexpr int PLANE = TROWS * RS;                 // 240 words per channel-word plane
constexpr long long PIXWORDS = (long long)Nn * HP * WPAD * WORDS;
}

__device__ uint32_t g_s1[Nn * HP * WPAD * WORDS];
__device__ uint32_t g_z1[Nn * HP * WPAD * WORDS];
__device__ uint32_t g_s2[Nn * HP * WPAD * WORDS];
__device__ uint32_t g_z2[Nn * HP * WPAD * WORDS];
__device__ uint32_t g_wb1[C * KW];
__device__ uint32_t g_wb2[C * KW];
__device__ float g_sc1[C], g_sh1[C], g_sc2[C], g_sh2[C];

// Full adder: 3 words -> sum (weight w) + carry (weight 2w). One LOP3 each.
__device__ __forceinline__ void fa(uint32_t a, uint32_t b, uint32_t c,
                                   uint32_t& s, uint32_t& cy) {
    s = a ^ b ^ c;
    cy = (a & b) | (c & (a | b));
}
__device__ __forceinline__ void madacc2(int& a, int p) {  // a += 2*p (fma pipe)
    asm("mad.lo.s32 %0, %1, 2, %0;" : "+r"(a) : "r"(p));
}
__device__ __forceinline__ void madacc4(int& a, int p) {  // a += 4*p (fma pipe)
    asm("mad.lo.s32 %0, %1, 4, %0;" : "+r"(a) : "r"(p));
}
__device__ __forceinline__ int madn2(int acc, int d0) {   // d0 - 2*acc (fma pipe)
    int r;
    asm("mad.lo.s32 %0, %1, -2, %2;" : "=r"(r) : "r"(acc), "r"(d0));
    return r;
}

__global__ void k_zero_nz() {
    long long stride = (long long)gridDim.x * blockDim.x;
    for (long long i = blockIdx.x * (long long)blockDim.x + threadIdx.x;
         i < PIXWORDS; i += stride) {
        g_z1[i] = 0u;
        g_z2[i] = 0u;
    }
}

// Pack input activations: grid (H, N), block (W=56, WORDS=8).
__global__ void k_pack_x(const float* __restrict__ x) {
    const int h = blockIdx.x, n = blockIdx.y;
    const int w = threadIdx.x, wd = threadIdx.y;
    const float* xp = x + (((long long)n * C + wd * 32) * H + h) * W + w;
    uint32_t s = 0, z = 0;
#pragma unroll
    for (int ci = 0; ci < 32; ci++) {
        float v = xp[(long long)ci * (H * W)];
        s |= (v > 0.f ? 1u : 0u) << ci;
        z |= (v != 0.f ? 1u : 0u) << ci;
    }
    long long idx = (((long long)n * HP + (h + 1)) * WPAD + (w + 1)) * WORDS + wd;
    g_s1[idx] = s;
    g_z1[idx] = z;
}

// Pack weights: grid (C), block (WORDS=8, 9 taps).
__global__ void k_pack_w(const float* __restrict__ w, int which) {
    uint32_t* __restrict__ outw = which ? g_wb2 : g_wb1;
    const int co = blockIdx.x, wd = threadIdx.x, tap = threadIdx.y;
    uint32_t s = 0;
#pragma unroll
    for (int ci = 0; ci < 32; ci++)
        s |= (w[(((long long)co * C) + wd * 32 + ci) * 9 + tap] > 0.f ? 1u : 0u) << ci;
    outw[co * KW + tap * WORDS + wd] = s;
}

__global__ void k_prep_bn(const float* __restrict__ g, const float* __restrict__ b,
                          const float* __restrict__ m, const float* __restrict__ v,
                          int which) {
    int c = threadIdx.x;
    float sc = g[c] * rsqrtf(v[c] + BN_EPS);
    float sh = b[c] - m[c] * sc;
    if (which) { g_sc2[c] = sc; g_sh2[c] = sh; }
    else       { g_sc1[c] = sc; g_sh1[c] = sh; }
}

// Binary conv + BN (+ re-binarize or residual/clip), CSA popcount.
// 2-D lane map: lane -> (wl = lane&7, rl = lane>>3): 8 w-cols x 4 rows, zero waste.
// Grid: (W/8=7, H/4=14, N). Block: 256 = 8 warps; warp = one 32-co channel word.
template <int STAGE>
__global__ __launch_bounds__(256, 2) void k_bconv(
    const float* __restrict__ xres, float* __restrict__ out) {
    const uint32_t* __restrict__ sIn = (STAGE == 1) ? g_s1 : g_s2;
    const uint32_t* __restrict__ zIn = (STAGE == 1) ? g_z1 : g_z2;
    const uint32_t* __restrict__ wb = (STAGE == 1) ? g_wb1 : g_wb2;
    const float* __restrict__ gsc = (STAGE == 1) ? g_sc1 : g_sc2;
    const float* __restrict__ gsh = (STAGE == 1) ? g_sh1 : g_sh2;

    __shared__ uint32_t xs[WORDS * PLANE];
    __shared__ uint32_t xz[WORDS * PLANE];
    __shared__ float scs[C], shs[C];

    const int w0 = blockIdx.x * 8, h0 = blockIdx.y * 4, n = blockIdx.z;
    const int tid = threadIdx.x;

    // Tile: 6 rows x 10 cols x 8 words, all reads inside the padded array.
    for (int i = tid; i < WORDS * TROWS * 10; i += 256) {
        int wd = i & 7, p = i >> 3;
        int col = p % 10, row = p / 10;
        long long gi = (((long long)n * HP + (h0 + row)) * WPAD + (w0 + col)) * WORDS + wd;
        xs[wd * PLANE + row * RS + col] = sIn[gi];
        xz[wd * PLANE + row * RS + col] = zIn[gi];
    }
    if (tid < C) { scs[tid] = gsc[tid]; shs[tid] = gsh[tid]; }
    __syncthreads();

    const int lane = tid & 31, wid = tid >> 5;
    const int wl = lane & 7, rl = lane >> 3;
    const int lbase = rl * RS + wl;
    const int oh = h0 + rl, ow = w0 + wl;

    // base = sum popc(nz) over this lane's 72-word window (shared by all co).
    int base = 0;
    for (int g = 0; g < 8; g++) {
        int off[9];
#pragma unroll
        for (int q = 0; q < 9; q++) {
            int k = g * 9 + q;
            int wd = k & 7, tap = k >> 3;
            off[q] = wd * PLANE + (tap / 3) * RS + (tap % 3) + lbase;
        }
        uint32_t s0, c0, s1, c1, s2, c2, S, C2, S2, C4;
        fa(xz[off[0]], xz[off[1]], xz[off[2]], s0, c0);
        fa(xz[off[3]], xz[off[4]], xz[off[5]], s1, c1);
        fa(xz[off[6]], xz[off[7]], xz[off[8]], s2, c2);
        fa(s0, s1, s2, S, C2);
        fa(c0, c1, c2, S2, C4);
        base += __popc(S);
        madacc2(base, __popc(C2) + __popc(S2));
        madacc4(base, __popc(C4));
    }

    uint32_t osig = 0u, onz = 0u;

    for (int j0 = 0; j0 < 32; j0 += 4) {
        int acc[4];
#pragma unroll
        for (int jj = 0; jj < 4; jj++) acc[jj] = 0;

        const uint32_t* wp = wb + (wid * 32 + j0) * KW;
        for (int g = 0; g < 8; g++) {
            uint32_t wk[4][9];
#pragma unroll
            for (int c4 = 0; c4 < 4; c4++)
#pragma unroll
                for (int t = 0; t < 9; t++) wk[c4][t] = __ldg(wp + c4 * KW + g * 9 + t);
            int off[9];
#pragma unroll
            for (int q = 0; q < 9; q++) {
                int k = g * 9 + q;
                int wd = k & 7, tap = k >> 3;
                off[q] = wd * PLANE + (tap / 3) * RS + (tap % 3) + lbase;
            }
            uint32_t sA[4][3], cA[4][3];
#pragma unroll
            for (int t3 = 0; t3 < 3; t3++) {
                uint32_t sx0 = xs[off[t3 * 3 + 0]], zx0 = xz[off[t3 * 3 + 0]];
                uint32_t sx1 = xs[off[t3 * 3 + 1]], zx1 = xz[off[t3 * 3 + 1]];
                uint32_t sx2 = xs[off[t3 * 3 + 2]], zx2 = xz[off[t3 * 3 + 2]];
#pragma unroll
                for (int c4 = 0; c4 < 4; c4++)
                    fa(zx0 & (sx0 ^ wk[c4][t3 * 3 + 0]),
                       zx1 & (sx1 ^ wk[c4][t3 * 3 + 1]),
                       zx2 & (sx2 ^ wk[c4][t3 * 3 + 2]),
                       sA[c4][t3], cA[c4][t3]);
            }
#pragma unroll
            for (int c4 = 0; c4 < 4; c4++) {
                uint32_t S, C2, S2, C4w;
                fa(sA[c4][0], sA[c4][1], sA[c4][2], S, C2);
                fa(cA[c4][0], cA[c4][1], cA[c4][2], S2, C4w);
                int a = acc[c4];
                a += __popc(S);
                madacc2(a, __popc(C2) + __popc(S2));
                madacc4(a, __popc(C4w));
                acc[c4] = a;
            }
        }

#pragma unroll
        for (int jj = 0; jj < 4; jj++) {
            const int co = wid * 32 + j0 + jj;
            const int dot = madn2(acc[jj], base);
            const float t = fmaf((float)dot, scs[co], shs[co]);
            if (STAGE == 1) {
                osig |= (t > 0.f ? 1u : 0u) << (j0 + jj);
                onz |= (t != 0.f ? 1u : 0u) << (j0 + jj);
            } else {
                long long oi = (((long long)n * C + co) * H + oh) * W + ow;
                float v = t + xres[oi];
                out[oi] = fminf(1.f, fmaxf(-1.f, v));
            }
        }
    }

    if (STAGE == 1) {
        long long gi = (((long long)n * HP + (oh + 1)) * WPAD + (ow + 1)) * WORDS + wid;
        g_s2[gi] = osig;
        g_z2[gi] = onz;
    }
}

extern "C" void kernel_launch(void* const* d_in, const int* in_sizes, int n_in,
                              void* d_out, int out_size) {
    (void)in_sizes; (void)n_in; (void)out_size;
    const float* x = (const float*)d_in[0];
    const float* w1 = (const float*)d_in[1];
    const float* g1 = (const float*)d_in[2];
    const float* b1 = (const float*)d_in[3];
    const float* m1 = (const float*)d_in[4];
    const float* v1 = (const float*)d_in[5];
    const float* w2 = (const float*)d_in[6];
    const float* g2 = (const float*)d_in[7];
    const float* b2 = (const float*)d_in[8];
    const float* m2 = (const float*)d_in[9];
    const float* v2 = (const float*)d_in[10];
    float* out = (float*)d_out;

    dim3 grid(W / 8, H / 4, Nn);
    k_zero_nz<<<1024, 256>>>();                        // 1
    k_pack_x<<<dim3(H, Nn), dim3(W, WORDS)>>>(x);      // 2
    k_pack_w<<<C, dim3(WORDS, 9)>>>(w1, 0);            // 3
    k_pack_w<<<C, dim3(WORDS, 9)>>>(w2, 1);            // 4
    k_prep_bn<<<1, C>>>(g1, b1, m1, v1, 0);            // 5
    k_bconv<1><<<grid, 256>>>(x, out);                 // 6
    k_prep_bn<<<1, C>>>(g2, b2, m2, v2, 1);            // 7
    k_bconv<2><<<grid, 256>>>(x, out);                 // 8
}

// round 12
// speedup vs baseline: 1.6002x; 1.6002x over previous
#include <cuda_runtime.h>
#include <stdint.h>

#define BN_EPS 1e-5f

namespace {
constexpr int Nn = 64, C = 256, H = 56, W = 56;
constexpr int PD = 58;             // padded dim
constexpr int WORDS = 8;           // channel words
constexpr int TB = 4;              // output rows per block
constexpr int TR = TB + 2;         // tile rows (with halo)
constexpr int TILE_U2 = WORDS * TR * PD;          // 2784 uint2
constexpr int ZC_OFF = TILE_U2 * 8;               // 22272 B
constexpr int SB_OFF = ZC_OFF + TR * PD * 4;      // + 1392 -> 23664
constexpr int STG_OFF = SB_OFF + TB * W * 4;      // + 896 -> 24560
constexpr int DYN1 = STG_OFF;                     // conv1: 24560 B
constexpr int DYN2 = STG_OFF + C * 57 * 4;        // conv2: + 58368 -> 82928 B
}

// Packed (sign, nonzero) bitplanes, zero-padded borders. uint2 = (s, z).
__device__ uint2 g_p1[(size_t)Nn * PD * PD * WORDS];
__device__ uint2 g_p2[(size_t)Nn * PD * PD * WORDS];
__device__ uint32_t g_wb1[C * 72];   // [co][wd][tap]
__device__ uint32_t g_wb2[C * 72];
__device__ float g_sc1[C], g_sh1[C], g_sc2[C], g_sh2[C];

__device__ __forceinline__ void fa(uint32_t a, uint32_t b, uint32_t c,
                                   uint32_t& s, uint32_t& cy) {
    s = a ^ b ^ c;
    cy = (a & b) | (c & (a | b));
}
__device__ __forceinline__ void madacc2(int& a, int p) {  // a += 2*p (fma pipe)
    asm("mad.lo.s32 %0, %1, 2, %0;" : "+r"(a) : "r"(p));
}
__device__ __forceinline__ void madacc4(int& a, int p) {  // a += 4*p (fma pipe)
    asm("mad.lo.s32 %0, %1, 4, %0;" : "+r"(a) : "r"(p));
}
__device__ __forceinline__ int madn2(int acc, int d0) {   // d0 - 2*acc (fma pipe)
    int r;
    asm("mad.lo.s32 %0, %1, -2, %2;" : "=r"(r) : "r"(acc), "r"(d0));
    return r;
}

__global__ void k_zero() {
    size_t tot = (size_t)Nn * PD * PD * WORDS / 2;  // uint4 count
    size_t stride = (size_t)gridDim.x * blockDim.x;
    uint4 z = {0u, 0u, 0u, 0u};
    for (size_t i = blockIdx.x * (size_t)blockDim.x + threadIdx.x; i < tot; i += stride) {
        ((uint4*)g_p1)[i] = z;
        ((uint4*)g_p2)[i] = z;
    }
}

// grid (H, N), block (W=56, WORDS=8)
__global__ void k_pack_x(const float* __restrict__ x) {
    const int h = blockIdx.x, n = blockIdx.y;
    const int w = threadIdx.x, wd = threadIdx.y;
    const float* xp = x + (((size_t)n * C + wd * 32) * H + h) * W + w;
    uint32_t s = 0, z = 0;
#pragma unroll
    for (int ci = 0; ci < 32; ci++) {
        float v = xp[(size_t)ci * (H * W)];
        s |= (v > 0.f ? 1u : 0u) << ci;
        z |= (v != 0.f ? 1u : 0u) << ci;
    }
    g_p1[(((size_t)n * PD + (h + 1)) * PD + (w + 1)) * WORDS + wd] = make_uint2(s, z);
}

// grid C, block (WORDS=8, 9): layout [co][wd][tap]
__global__ void k_pack_w(const float* __restrict__ w, int which) {
    uint32_t* __restrict__ outw = which ? g_wb2 : g_wb1;
    const int co = blockIdx.x, wd = threadIdx.x, tap = threadIdx.y;
    uint32_t s = 0;
#pragma unroll
    for (int ci = 0; ci < 32; ci++)
        s |= (w[(((size_t)co * C) + wd * 32 + ci) * 9 + tap] > 0.f ? 1u : 0u) << ci;
    outw[co * 72 + wd * 9 + tap] = s;
}

__global__ void k_prep_bn(const float* __restrict__ g, const float* __restrict__ b,
                          const float* __restrict__ m, const float* __restrict__ v,
                          int which) {
    int c = threadIdx.x;
    float sc = g[c] * rsqrtf(v[c] + BN_EPS);
    float sh = b[c] - m[c] * sc;
    if (which) { g_sc2[c] = sc; g_sh2[c] = sh; }
    else       { g_sc1[c] = sc; g_sh1[c] = sh; }
}

// Co-stationary binary conv: lane = output channel, weights register-resident.
// Grid (H/TB=14, N). Block 256 = 8 warps (warp wid covers co = wid*32+lane).
// Streams TB*56 pixels from a (TR x 58) shared tile of packed (s,z) words.
template <int STAGE>
__global__ __launch_bounds__(256, 2) void k_bconv(
    const float* __restrict__ xres, float* __restrict__ out) {
    const uint2* __restrict__ pin = (STAGE == 1) ? g_p1 : g_p2;
    const uint32_t* __restrict__ wb = (STAGE == 1) ? g_wb1 : g_wb2;

    extern __shared__ char sm[];
    uint2* tile = (uint2*)sm;                 // [wd][TR][58]
    int* zc = (int*)(sm + ZC_OFF);            // [TR*58]
    int* sbase = (int*)(sm + SB_OFF);         // [TB*56]
    float* stg = (float*)(sm + STG_OFF);      // conv2: [C][57]

    const int rg = blockIdx.x, n = blockIdx.y, tid = threadIdx.x;
    const int h0 = rg * TB;
    const int lane = tid & 31, wid = tid >> 5;
    const int co = wid * 32 + lane;

    // Per-lane weights (72 words) and BN coefficients: register-resident.
    uint32_t wk[72];
#pragma unroll
    for (int t = 0; t < 72; t++) wk[t] = __ldg(wb + co * 72 + t);
    const float sc = __ldg(((STAGE == 1) ? g_sc1 : g_sc2) + co);
    const float sh = __ldg(((STAGE == 1) ? g_sh1 : g_sh2) + co);

    // Load tile (all reads inside padded array; no bounds checks).
    for (int i = tid; i < WORDS * TR * PD; i += 256) {
        int wd = i & 7, p = i >> 3;
        int tr = p / PD, tc = p - tr * PD;
        tile[wd * (TR * PD) + p] =
            pin[(((size_t)n * PD + (h0 + tr)) * PD + tc) * WORDS + wd];
    }
    __syncthreads();
    // zc[p] = sum_wd popc(z)
    for (int p = tid; p < TR * PD; p += 256) {
        int s = 0;
#pragma unroll
        for (int wd = 0; wd < 8; wd++) s += __popc(tile[wd * (TR * PD) + p].y);
        zc[p] = s;
    }
    __syncthreads();
    // sbase[pixel] = 3x3 box-sum of zc  (the warp-uniform "base" term)
    for (int p = tid; p < TB * W; p += 256) {
        int r = p / W, w = p - r * W;
        int s = 0;
#pragma unroll
        for (int dh = 0; dh < 3; dh++)
#pragma unroll
            for (int dw = 0; dw < 3; dw++) s += zc[(r + dh) * PD + w + dw];
        sbase[p] = s;
    }
    __syncthreads();

    for (int r = 0; r < TB; r++) {
        for (int w = 0; w < W; w++) {
            int acc = 0;
#pragma unroll
            for (int wd = 0; wd < 8; wd++) {
                const uint2* tp = tile + wd * (TR * PD) + r * PD + w;
                uint2 x0 = tp[0], x1 = tp[1], x2 = tp[2];
                uint2 x3 = tp[PD], x4 = tp[PD + 1], x5 = tp[PD + 2];
                uint2 x6 = tp[2 * PD], x7 = tp[2 * PD + 1], x8 = tp[2 * PD + 2];
                const uint32_t* wq = wk + wd * 9;
                uint32_t m0 = x0.y & (x0.x ^ wq[0]);
                uint32_t m1 = x1.y & (x1.x ^ wq[1]);
                uint32_t m2 = x2.y & (x2.x ^ wq[2]);
                uint32_t m3 = x3.y & (x3.x ^ wq[3]);
                uint32_t m4 = x4.y & (x4.x ^ wq[4]);
                uint32_t m5 = x5.y & (x5.x ^ wq[5]);
                uint32_t m6 = x6.y & (x6.x ^ wq[6]);
                uint32_t m7 = x7.y & (x7.x ^ wq[7]);
                uint32_t m8 = x8.y & (x8.x ^ wq[8]);
                uint32_t s0, c0, s1, c1, s2, c2, S, C2, S2, C4;
                fa(m0, m1, m2, s0, c0);
                fa(m3, m4, m5, s1, c1);
                fa(m6, m7, m8, s2, c2);
                fa(s0, s1, s2, S, C2);
                fa(c0, c1, c2, S2, C4);
                acc += __popc(S);
                madacc2(acc, __popc(C2) + __popc(S2));
                madacc4(acc, __popc(C4));
            }
            const int dot = madn2(acc, sbase[r * W + w]);
            const float t = fmaf((float)dot, sc, sh);
            if (STAGE == 1) {
                uint32_t sig = __ballot_sync(0xffffffffu, t > 0.f);
                uint32_t nz = __ballot_sync(0xffffffffu, t != 0.f);
                if (lane == 0)
                    g_p2[(((size_t)n * PD + (h0 + r + 1)) * PD + (w + 1)) * WORDS + wid] =
                        make_uint2(sig, nz);
            } else {
                stg[co * 57 + w] = t;
            }
        }
        if (STAGE == 2) {
            __syncthreads();
            const int h = h0 + r;
            for (int i = tid; i < C * W; i += 256) {
                int c2 = i / W, w2 = i - c2 * W;
                size_t oi = (((size_t)n * C + c2) * H + h) * W + w2;
                float v = stg[c2 * 57 + w2] + xres[oi];
                out[oi] = fminf(1.f, fmaxf(-1.f, v));
            }
            __syncthreads();
        }
    }
}

extern "C" void kernel_launch(void* const* d_in, const int* in_sizes, int n_in,
                              void* d_out, int out_size) {
    (void)in_sizes; (void)n_in; (void)out_size;
    const float* x = (const float*)d_in[0];
    const float* w1 = (const float*)d_in[1];
    const float* g1 = (const float*)d_in[2];
    const float* b1 = (const float*)d_in[3];
    const float* m1 = (const float*)d_in[4];
    const float* v1 = (const float*)d_in[5];
    const float* w2 = (const float*)d_in[6];
    const float* g2 = (const float*)d_in[7];
    const float* b2 = (const float*)d_in[8];
    const float* m2 = (const float*)d_in[9];
    const float* v2 = (const float*)d_in[10];
    float* out = (float*)d_out;

    cudaFuncSetAttribute(k_bconv<1>, cudaFuncAttributeMaxDynamicSharedMemorySize, DYN1);
    cudaFuncSetAttribute(k_bconv<2>, cudaFuncAttributeMaxDynamicSharedMemorySize, DYN2);

    dim3 grid(H / TB, Nn);
    k_zero<<<2048, 256>>>();
    k_pack_x<<<dim3(H, Nn), dim3(W, WORDS)>>>(x);
    k_pack_w<<<C, dim3(WORDS, 9)>>>(w1, 0);
    k_pack_w<<<C, dim3(WORDS, 9)>>>(w2, 1);
    k_prep_bn<<<1, C>>>(g1, b1, m1, v1, 0);
    k_bconv<1><<<grid, 256, DYN1>>>(x, out);
    k_prep_bn<<<1, C>>>(g2, b2, m2, v2, 1);
    k_bconv<2><<<grid, 256, DYN2>>>(x, out);
}

// round 13
// speedup vs baseline: 1.7374x; 1.0857x over previous
#include <cuda_runtime.h>
#include <stdint.h>

#define BN_EPS 1e-5f

namespace {
constexpr int Nn = 64, C = 256, H = 56, W = 56;
constexpr int PD = 58;             // padded dim
constexpr int WORDS = 8;           // channel words
constexpr int TB = 4;              // output rows per block
constexpr int TR = TB + 2;         // tile rows (with halo)
constexpr int TRPD = TR * PD;      // 348
constexpr int TILE_U2 = WORDS * TRPD;             // 2784 uint2
constexpr int ZC_OFF = TILE_U2 * 8;               // 22272 B
constexpr int SB_OFF = ZC_OFF + TRPD * 4;         // + 1392 -> 23664
constexpr int STG_OFF = SB_OFF + TB * W * 4;      // + 896 -> 24560
constexpr int DYN1 = STG_OFF;                     // conv1: 24560 B
constexpr int DYN2 = STG_OFF + C * 57 * 4;        // conv2: + 58368 -> 82928 B
}

// Packed (sign, nonzero) bitplanes, zero-padded borders. uint2 = (s, z).
__device__ uint2 g_p1[(size_t)Nn * PD * PD * WORDS];
__device__ uint2 g_p2[(size_t)Nn * PD * PD * WORDS];
__device__ uint32_t g_wb1[C * 72];   // [co][wd][tap]
__device__ uint32_t g_wb2[C * 72];
__device__ float g_sc1[C], g_sh1[C], g_sc2[C], g_sh2[C];

__device__ __forceinline__ void fa(uint32_t a, uint32_t b, uint32_t c,
                                   uint32_t& s, uint32_t& cy) {
    s = a ^ b ^ c;
    cy = (a & b) | (c & (a | b));
}
__device__ __forceinline__ void madacc1(int& a, int p) {  // a += p (fma pipe)
    asm("mad.lo.s32 %0, %1, 1, %0;" : "+r"(a) : "r"(p));
}
__device__ __forceinline__ void madacc2(int& a, int p) {  // a += 2*p (fma pipe)
    asm("mad.lo.s32 %0, %1, 2, %0;" : "+r"(a) : "r"(p));
}
__device__ __forceinline__ void madacc4(int& a, int p) {  // a += 4*p (fma pipe)
    asm("mad.lo.s32 %0, %1, 4, %0;" : "+r"(a) : "r"(p));
}
__device__ __forceinline__ int madn2(int acc, int d0) {   // d0 - 2*acc (fma pipe)
    int r;
    asm("mad.lo.s32 %0, %1, -2, %2;" : "=r"(r) : "r"(acc), "r"(d0));
    return r;
}

__global__ void k_zero() {
    size_t tot = (size_t)Nn * PD * PD * WORDS / 2;  // uint4 count
    size_t stride = (size_t)gridDim.x * blockDim.x;
    uint4 z = {0u, 0u, 0u, 0u};
    for (size_t i = blockIdx.x * (size_t)blockDim.x + threadIdx.x; i < tot; i += stride) {
        ((uint4*)g_p1)[i] = z;
        ((uint4*)g_p2)[i] = z;
    }
}

// grid (H, N), block (W=56, WORDS=8)
__global__ void k_pack_x(const float* __restrict__ x) {
    const int h = blockIdx.x, n = blockIdx.y;
    const int w = threadIdx.x, wd = threadIdx.y;
    const float* xp = x + (((size_t)n * C + wd * 32) * H + h) * W + w;
    uint32_t s = 0, z = 0;
#pragma unroll
    for (int ci = 0; ci < 32; ci++) {
        float v = xp[(size_t)ci * (H * W)];
        s |= (v > 0.f ? 1u : 0u) << ci;
        z |= (v != 0.f ? 1u : 0u) << ci;
    }
    g_p1[(((size_t)n * PD + (h + 1)) * PD + (w + 1)) * WORDS + wd] = make_uint2(s, z);
}

// grid C, block (WORDS=8, 9): layout [co][wd][tap]
__global__ void k_pack_w(const float* __restrict__ w, int which) {
    uint32_t* __restrict__ outw = which ? g_wb2 : g_wb1;
    const int co = blockIdx.x, wd = threadIdx.x, tap = threadIdx.y;
    uint32_t s = 0;
#pragma unroll
    for (int ci = 0; ci < 32; ci++)
        s |= (w[(((size_t)co * C) + wd * 32 + ci) * 9 + tap] > 0.f ? 1u : 0u) << ci;
    outw[co * 72 + wd * 9 + tap] = s;
}

__global__ void k_prep_bn(const float* __restrict__ g, const float* __restrict__ b,
                          const float* __restrict__ m, const float* __restrict__ v,
                          int which) {
    int c = threadIdx.x;
    float sc = g[c] * rsqrtf(v[c] + BN_EPS);
    float sh = b[c] - m[c] * sc;
    if (which) { g_sc2[c] = sc; g_sh2[c] = sh; }
    else       { g_sc1[c] = sc; g_sh1[c] = sh; }
}

// Co-stationary binary conv: lane = output channel, weights register-resident.
// w unrolled x2: pixel pair shares 2/3 of the x window; 2 independent chains.
// Grid (H/TB=14, N). Block 256 = 8 warps (warp wid covers co = wid*32+lane).
template <int STAGE>
__global__ __launch_bounds__(256, 2) void k_bconv(
    const float* __restrict__ xres, float* __restrict__ out) {
    const uint2* __restrict__ pin = (STAGE == 1) ? g_p1 : g_p2;
    const uint32_t* __restrict__ wb = (STAGE == 1) ? g_wb1 : g_wb2;

    extern __shared__ char sm[];
    uint2* tile = (uint2*)sm;                 // [wd][TR][58]
    int* zc = (int*)(sm + ZC_OFF);            // [TR*58]
    int* sbase = (int*)(sm + SB_OFF);         // [TB*56]
    float* stg = (float*)(sm + STG_OFF);      // conv2: [C][57]

    const int rg = blockIdx.x, n = blockIdx.y, tid = threadIdx.x;
    const int h0 = rg * TB;
    const int lane = tid & 31, wid = tid >> 5;
    const int co = wid * 32 + lane;

    // Per-lane weights (72 words) and BN coefficients: register-resident.
    uint32_t wk[72];
#pragma unroll
    for (int t = 0; t < 72; t++) wk[t] = __ldg(wb + co * 72 + t);
    const float sc = __ldg(((STAGE == 1) ? g_sc1 : g_sc2) + co);
    const float sh = __ldg(((STAGE == 1) ? g_sh1 : g_sh2) + co);

    // Load tile as uint4 (pairs of uint2); layout is [pix][wd], wd even-aligned.
    for (int i = tid; i < WORDS * TRPD / 2; i += 256) {
        int wd2 = i & 3, p = i >> 2;   // wd2 = wd/2
        uint4 v = ((const uint4*)(pin + (((size_t)n * PD + h0) * PD) * WORDS))[p * 4 + wd2];
        uint2* dst0 = tile + (2 * wd2) * TRPD + p;
        dst0[0] = make_uint2(v.x, v.y);
        dst0[TRPD] = make_uint2(v.z, v.w);
    }
    __syncthreads();
    // zc[p] = sum_wd popc(z)
    for (int p = tid; p < TRPD; p += 256) {
        int s = 0;
#pragma unroll
        for (int wd = 0; wd < 8; wd++) s += __popc(tile[wd * TRPD + p].y);
        zc[p] = s;
    }
    __syncthreads();
    // sbase[pixel] = 3x3 box-sum of zc (warp-uniform "base" term)
    for (int p = tid; p < TB * W; p += 256) {
        int r = p / W, w = p - r * W;
        int s = 0;
#pragma unroll
        for (int dh = 0; dh < 3; dh++)
#pragma unroll
            for (int dw = 0; dw < 3; dw++) s += zc[(r + dh) * PD + w + dw];
        sbase[p] = s;
    }
    __syncthreads();

    for (int r = 0; r < TB; r++) {
#pragma unroll 1
        for (int w = 0; w < W; w += 2) {
            int acc0 = 0, acc1 = 0;
#pragma unroll
            for (int wd = 0; wd < 8; wd++) {
                const uint2* tp = tile + wd * TRPD + r * PD + w;
                uint2 xa0 = tp[0], xa1 = tp[1], xa2 = tp[2], xa3 = tp[3];
                uint2 xb0 = tp[PD], xb1 = tp[PD + 1], xb2 = tp[PD + 2], xb3 = tp[PD + 3];
                uint2 xc0 = tp[2 * PD], xc1 = tp[2 * PD + 1], xc2 = tp[2 * PD + 2],
                      xc3 = tp[2 * PD + 3];
                const uint32_t* wq = wk + wd * 9;
                // pixel w
                {
                    uint32_t m0 = xa0.y & (xa0.x ^ wq[0]);
                    uint32_t m1 = xa1.y & (xa1.x ^ wq[1]);
                    uint32_t m2 = xa2.y & (xa2.x ^ wq[2]);
                    uint32_t m3 = xb0.y & (xb0.x ^ wq[3]);
                    uint32_t m4 = xb1.y & (xb1.x ^ wq[4]);
                    uint32_t m5 = xb2.y & (xb2.x ^ wq[5]);
                    uint32_t m6 = xc0.y & (xc0.x ^ wq[6]);
                    uint32_t m7 = xc1.y & (xc1.x ^ wq[7]);
                    uint32_t m8 = xc2.y & (xc2.x ^ wq[8]);
                    uint32_t s0, c0, s1, c1, s2, c2, S, C2, S2, C4;
                    fa(m0, m1, m2, s0, c0);
                    fa(m3, m4, m5, s1, c1);
                    fa(m6, m7, m8, s2, c2);
                    fa(s0, s1, s2, S, C2);
                    fa(c0, c1, c2, S2, C4);
                    madacc1(acc0, __popc(S));
                    madacc2(acc0, __popc(C2));
                    madacc2(acc0, __popc(S2));
                    madacc4(acc0, __popc(C4));
                }
                // pixel w+1
                {
                    uint32_t m0 = xa1.y & (xa1.x ^ wq[0]);
                    uint32_t m1 = xa2.y & (xa2.x ^ wq[1]);
                    uint32_t m2 = xa3.y & (xa3.x ^ wq[2]);
                    uint32_t m3 = xb1.y & (xb1.x ^ wq[3]);
                    uint32_t m4 = xb2.y & (xb2.x ^ wq[4]);
                    uint32_t m5 = xb3.y & (xb3.x ^ wq[5]);
                    uint32_t m6 = xc1.y & (xc1.x ^ wq[6]);
                    uint32_t m7 = xc2.y & (xc2.x ^ wq[7]);
                    uint32_t m8 = xc3.y & (xc3.x ^ wq[8]);
                    uint32_t s0, c0, s1, c1, s2, c2, S, C2, S2, C4;
                    fa(m0, m1, m2, s0, c0);
                    fa(m3, m4, m5, s1, c1);
                    fa(m6, m7, m8, s2, c2);
                    fa(s0, s1, s2, S, C2);
                    fa(c0, c1, c2, S2, C4);
                    madacc1(acc1, __popc(S));
                    madacc2(acc1, __popc(C2));
                    madacc2(acc1, __popc(S2));
                    madacc4(acc1, __popc(C4));
                }
            }
            const int dot0 = madn2(acc0, sbase[r * W + w]);
            const int dot1 = madn2(acc1, sbase[r * W + w + 1]);
            const float t0 = fmaf((float)dot0, sc, sh);
            const float t1 = fmaf((float)dot1, sc, sh);
            if (STAGE == 1) {
                uint32_t sig0 = __ballot_sync(0xffffffffu, t0 > 0.f);
                uint32_t nz0 = __ballot_sync(0xffffffffu, t0 != 0.f);
                uint32_t sig1 = __ballot_sync(0xffffffffu, t1 > 0.f);
                uint32_t nz1 = __ballot_sync(0xffffffffu, t1 != 0.f);
                if (lane == 0) {
                    size_t gi = (((size_t)n * PD + (h0 + r + 1)) * PD + (w + 1)) * WORDS + wid;
                    g_p2[gi] = make_uint2(sig0, nz0);
                    g_p2[gi + WORDS] = make_uint2(sig1, nz1);
                }
            } else {
                stg[co * 57 + w] = t0;
                stg[co * 57 + w + 1] = t1;
            }
        }
        if (STAGE == 2) {
            __syncthreads();
            const int h = h0 + r;
            for (int i = tid; i < C * W; i += 256) {
                int c2 = i / W, w2 = i - c2 * W;
                size_t oi = (((size_t)n * C + c2) * H + h) * W + w2;
                float v = stg[c2 * 57 + w2] + xres[oi];
                out[oi] = fminf(1.f, fmaxf(-1.f, v));
            }
            __syncthreads();
        }
    }
}

extern "C" void kernel_launch(void* const* d_in, const int* in_sizes, int n_in,
                              void* d_out, int out_size) {
    (void)in_sizes; (void)n_in; (void)out_size;
    const float* x = (const float*)d_in[0];
    const float* w1 = (const float*)d_in[1];
    const float* g1 = (const float*)d_in[2];
    const float* b1 = (const float*)d_in[3];
    const float* m1 = (const float*)d_in[4];
    const float* v1 = (const float*)d_in[5];
    const float* w2 = (const float*)d_in[6];
    const float* g2 = (const float*)d_in[7];
    const float* b2 = (const float*)d_in[8];
    const float* m2 = (const float*)d_in[9];
    const float* v2 = (const float*)d_in[10];
    float* out = (float*)d_out;

    cudaFuncSetAttribute(k_bconv<1>, cudaFuncAttributeMaxDynamicSharedMemorySize, DYN1);
    cudaFuncSetAttribute(k_bconv<2>, cudaFuncAttributeMaxDynamicSharedMemorySize, DYN2);

    dim3 grid(H / TB, Nn);
    k_zero<<<2048, 256>>>();
    k_pack_x<<<dim3(H, Nn), dim3(W, WORDS)>>>(x);
    k_pack_w<<<C, dim3(WORDS, 9)>>>(w1, 0);
    k_pack_w<<<C, dim3(WORDS, 9)>>>(w2, 1);
    k_prep_bn<<<1, C>>>(g1, b1, m1, v1, 0);
    k_bconv<1><<<grid, 256, DYN1>>>(x, out);
    k_prep_bn<<<1, C>>>(g2, b2, m2, v2, 1);
    k_bconv<2><<<grid, 256, DYN2>>>(x, out);
}